// round 12
// baseline (speedup 1.0000x reference)
#include <cuda_runtime.h>
#include <stdint.h>

#define NODES   100000
#define MAX_E   3200000
#define SCAN_BS 1024
#define NB      ((NODES + SCAN_BS - 1) / SCAN_BS)   // 98
#define DEN_FX  16777216.0f
#define NWIN    8      // 16-edge windows per warp
#define PKS     8      // pack smem stages
#define GSS     4      // gather smem stages

// ---------------- scratch ----------------
__device__ unsigned long long g_cd[NODES];
__device__ int   g_cursor[NODES];
__device__ float g_invden[NODES];
__device__ int   g_bsum[NB];
__device__ uint4 g_pack[MAX_E + 512];        // {eid, node, bits(w), 0}; padded w/ sentinels

// ---------------- helpers ----------------
__device__ __forceinline__ unsigned f2tf32(float f) {
    unsigned r;
    asm("cvt.rna.tf32.f32 %0, %1;" : "=r"(r) : "f"(f));
    return r;
}
__device__ __forceinline__ void mma_tf32(float& d0, float& d1, float& d2, float& d3,
                                         unsigned a0, unsigned a1, unsigned a2, unsigned a3,
                                         unsigned b0, unsigned b1) {
    asm volatile(
        "mma.sync.aligned.m16n8k8.row.col.f32.tf32.tf32.f32 "
        "{%0,%1,%2,%3}, {%4,%5,%6,%7}, {%8,%9}, {%0,%1,%2,%3};"
        : "+f"(d0), "+f"(d1), "+f"(d2), "+f"(d3)
        : "r"(a0), "r"(a1), "r"(a2), "r"(a3), "r"(b0), "r"(b1));
}
__device__ __forceinline__ void redadd(float* p, float v) {
    asm volatile("red.global.add.f32 [%0], %1;" :: "l"(p), "f"(v) : "memory");
}
__device__ __forceinline__ unsigned sptr(const void* p) {
    return (unsigned)__cvta_generic_to_shared(p);
}
#define CPA16(dst, src) asm volatile("cp.async.cg.shared.global [%0], [%1], 16;" :: "r"(dst), "l"(src))
#define CPCOMMIT()      asm volatile("cp.async.commit_group;" ::: "memory")
#define CPWAIT(n)       asm volatile("cp.async.wait_group %0;" :: "n"(n) : "memory")

// butterfly-sum over 4-lane group, lane c writes u-block mt==c. Skips sentinels.
__device__ __forceinline__ void seg_write(float a[4][2], int node, bool use_red,
                                          float* __restrict__ out, int c, int r4) {
#pragma unroll
    for (int mt = 0; mt < 4; mt++)
#pragma unroll
        for (int h = 0; h < 2; h++) {
            float v = a[mt][h];
            v += __shfl_xor_sync(0xffffffffu, v, 1);
            v += __shfl_xor_sync(0xffffffffu, v, 2);
            a[mt][h] = v;
        }
    if ((unsigned)node >= NODES) return;     // sentinel / invalid
    float vlo = (c == 0) ? a[0][0] : (c == 1) ? a[1][0] : (c == 2) ? a[2][0] : a[3][0];
    float vhi = (c == 0) ? a[0][1] : (c == 1) ? a[1][1] : (c == 2) ? a[2][1] : a[3][1];
    float* dst = out + (size_t)node * 64 + c * 16 + r4;
    if (use_red) { redadd(dst, vlo); redadd(dst + 8, vhi); }
    else         { dst[0] = vlo; dst[8] = vhi; }
}

// ---------------- K1: count + weight-sum + zero out[] ----------------
__global__ void k_count(const int* __restrict__ idx, const float* __restrict__ w,
                        float4* __restrict__ out4, int n4, int E) {
    int e = blockIdx.x * blockDim.x + threadIdx.x;
    for (int z = e; z < n4; z += gridDim.x * blockDim.x)
        out4[z] = make_float4(0.f, 0.f, 0.f, 0.f);
    if (e >= E) return;
    int n = idx[e];
    unsigned fx = __float2uint_rn(w[e] * DEN_FX);
    atomicAdd(&g_cd[n], (1ULL << 32) | (unsigned long long)fx);
}

// ---------------- K2: block-local scan + invden + g_cd re-zero ----------------
__global__ void k_scan1() {
    __shared__ int wsum[32];
    int t = threadIdx.x, b = blockIdx.x;
    int i = b * SCAN_BS + t;
    int lane = t & 31, wq = t >> 5;
    unsigned long long cd = (i < NODES) ? g_cd[i] : 0ULL;
    int v = (int)(cd >> 32);
    if (i < NODES) {
        g_cd[i] = 0ULL;
        g_invden[i] = __fdividef(DEN_FX, (float)(unsigned)(cd & 0xffffffffULL));
    }
    int x = v;
#pragma unroll
    for (int d = 1; d < 32; d <<= 1) {
        int y = __shfl_up_sync(0xffffffffu, x, d);
        if (lane >= d) x += y;
    }
    if (lane == 31) wsum[wq] = x;
    __syncthreads();
    if (wq == 0) {
        int s = wsum[lane];
#pragma unroll
        for (int d = 1; d < 32; d <<= 1) {
            int y = __shfl_up_sync(0xffffffffu, s, d);
            if (lane >= d) s += y;
        }
        wsum[lane] = s;
    }
    __syncthreads();
    int base = wq ? wsum[wq - 1] : 0;
    if (i < NODES) g_cursor[i] = base + x - v;
    if (t == 0) g_bsum[b] = wsum[31];
}

// ---------------- K3: scatter (inline bsum prefix) + sentinel padding ----------------
__global__ void k_scatter(const int* __restrict__ idx, const float* __restrict__ w,
                          int E, int Epad) {
    __shared__ int s_boff[128];
    __shared__ int s_wt[4];
    int t = threadIdx.x;
    int lane = t & 31, wq = t >> 5;
    int v = 0, x = 0;
    if (t < 128) {
        v = (t < NB) ? g_bsum[t] : 0;
        x = v;
#pragma unroll
        for (int d = 1; d < 32; d <<= 1) {
            int y = __shfl_up_sync(0xffffffffu, x, d);
            if (lane >= d) x += y;
        }
        if (lane == 31) s_wt[wq] = x;
    }
    __syncthreads();
    if (t < 128) {
        int addv = 0;
#pragma unroll
        for (int k = 0; k < 4; k++) if (k < wq) addv += s_wt[k];
        s_boff[t] = addv + x - v;
    }
    __syncthreads();
    int e = blockIdx.x * blockDim.x + t;
    if (e < Epad - E)                                    // sentinel tail
        g_pack[E + e] = make_uint4(0u, (unsigned)NODES, 0u, 0u);
    if (e >= E) return;
    int n = idx[e];
    int p = atomicAdd(&g_cursor[n], 1) + s_boff[n >> 10];
    g_pack[p] = make_uint4((unsigned)e, (unsigned)n, __float_as_uint(w[e]), 0u);
}

// ---------------- K4: cp.async-pipelined transposed MMA + register seg reduce ----------------
__global__ void __launch_bounds__(128, 7)
k_main(const float* __restrict__ emb, const float* __restrict__ cf,
       float* __restrict__ out, int E) {
    __shared__ __align__(16) uint4 s_pk[4][PKS][16];      // 8 KB
    __shared__ __align__(16) float s_gb[4][GSS][256];     // 16 KB

    int t = threadIdx.x, wp = t >> 5, l = t & 31;
    int c = l & 3, r4 = l >> 2;
    int wb = (blockIdx.x * 4 + wp) * (NWIN * 16);

    // --- A fragments, K-permuted (slot c holds k=4c+j, matching quarter-major B).
    //     A keeps cvt.rna (amortized over all windows); B below uses raw-f32
    //     truncation (tf32 MMA reads bits[31:13]) to kill per-window CVTs. ---
    unsigned A[4][2][4];
#pragma unroll
    for (int mt = 0; mt < 4; mt++)
#pragma unroll
        for (int kt = 0; kt < 2; kt++) {
            const float* p = emb + (mt * 16 + r4) * 16 + 4 * c + 2 * kt;
            A[mt][kt][0] = f2tf32(__ldg(p));
            A[mt][kt][1] = f2tf32(__ldg(p + 128));
            A[mt][kt][2] = f2tf32(__ldg(p + 1));
            A[mt][kt][3] = f2tf32(__ldg(p + 129));
        }

    int nback = -2, nfwd = -2;
    if (wb > 0)              nback = (int)__ldg(&g_pack[wb - 1]).y;
    if (wb + NWIN * 16 < E)  nfwd  = (int)__ldg(&g_pack[wb + NWIN * 16]).y;

    // --- prologue: packs for windows 0..6 (one group), then gathers 0..2 ---
    for (int i = l; i < 112; i += 32)
        CPA16(sptr(&s_pk[wp][i >> 4][i & 15]), g_pack + wb + i);
    CPCOMMIT();
    CPWAIT(0); __syncwarp();
#pragma unroll
    for (int g = 0; g < 3; g++) {
#pragma unroll
        for (int h = 0; h < 2; h++) {
            int i = l + h * 32;
            unsigned eid = s_pk[wp][g][i >> 2].x;
            CPA16(sptr(&s_gb[wp][g][i * 4]), cf + (size_t)eid * 16 + (i & 3) * 4);
        }
        CPCOMMIT();
    }

    float acc[4][2];
#pragma unroll
    for (int mt = 0; mt < 4; mt++) { acc[mt][0] = 0.f; acc[mt][1] = 0.f; }
    int acc_node = -1;
    bool first = true;
    int prev_last = 0;

#pragma unroll 1
    for (int j = 0; j < NWIN; j++) {
        CPWAIT(2); __syncwarp();               // gather j + packs through j+4 resident

        uint4* pkw = s_pk[wp][j & 7];
        int   nd = (int)pkw[l & 15].y;
        float w0 = __uint_as_float(pkw[r4].z);
        float w1 = __uint_as_float(pkw[8 + r4].z);
        int ndn = __shfl_down_sync(0xffffffffu, nd, 1);
        unsigned bm = __ballot_sync(0xffffffffu, (l < 15) && (nd != ndn)) & 0x7fffu;
        int node0 = __shfl_sync(0xffffffffu, nd, 0);

        // --- issue next loads (hidden under this window's compute) ---
        if (j + 3 < NWIN) {
            uint4* pks = s_pk[wp][(j + 3) & 7];
#pragma unroll
            for (int h = 0; h < 2; h++) {
                int i = l + h * 32;
                unsigned eid = pks[i >> 2].x;
                CPA16(sptr(&s_gb[wp][(j + 3) & 3][i * 4]), cf + (size_t)eid * 16 + (i & 3) * 4);
            }
        }
        if (j + 7 < NWIN) {
            if (l < 16)
                CPA16(sptr(&s_pk[wp][(j + 7) & 7][l]), g_pack + wb + (j + 7) * 16 + l);
        }
        CPCOMMIT();

        // --- B values from smem (quarter-major, conflict-free) ---
        const float* gw = s_gb[wp][j & 3];
        float4 B0 = *(const float4*)(gw + r4 * 16 + 4 * c);
        float4 B1 = *(const float4*)(gw + (8 + r4) * 16 + 4 * c);

        if (j == 0) acc_node = node0;
        else if (prev_last != node0) {
            seg_write(acc, acc_node, first && (nback == acc_node), out, c, r4);
            first = false;
#pragma unroll
            for (int mt = 0; mt < 4; mt++) { acc[mt][0] = 0.f; acc[mt][1] = 0.f; }
            acc_node = node0;
        }

#pragma unroll
        for (int et = 0; et < 2; et++) {
            if (et == 1 && (bm & 0x0080u)) {   // seam between edge 7 and 8
                seg_write(acc, acc_node, first && (nback == acc_node), out, c, r4);
                first = false;
#pragma unroll
                for (int mt = 0; mt < 4; mt++) { acc[mt][0] = 0.f; acc[mt][1] = 0.f; }
                acc_node = __shfl_sync(0xffffffffu, nd, 8);
            }

            float wv = et ? w1 : w0;
            float4 Bv = et ? B1 : B0;
            // raw f32 bits as tf32 (truncation) — no CVT in the hot loop
            unsigned b0 = __float_as_uint(Bv.x * wv);
            unsigned b1 = __float_as_uint(Bv.y * wv);
            unsigned b2 = __float_as_uint(Bv.z * wv);
            unsigned b3 = __float_as_uint(Bv.w * wv);

            float d[4][4];
#pragma unroll
            for (int mt = 0; mt < 4; mt++) {
                d[mt][0] = 0.f; d[mt][1] = 0.f; d[mt][2] = 0.f; d[mt][3] = 0.f;
                mma_tf32(d[mt][0], d[mt][1], d[mt][2], d[mt][3],
                         A[mt][0][0], A[mt][0][1], A[mt][0][2], A[mt][0][3], b0, b1);
                mma_tf32(d[mt][0], d[mt][1], d[mt][2], d[mt][3],
                         A[mt][1][0], A[mt][1][1], A[mt][1][2], A[mt][1][3], b2, b3);
                d[mt][0] = fmaxf(d[mt][0], 0.f);
                d[mt][1] = fmaxf(d[mt][1], 0.f);
                d[mt][2] = fmaxf(d[mt][2], 0.f);
                d[mt][3] = fmaxf(d[mt][3], 0.f);
            }

            unsigned tb = (bm >> (et * 8)) & 0x7fu;
            if (tb == 0) {
#pragma unroll
                for (int mt = 0; mt < 4; mt++) {
                    acc[mt][0] += d[mt][0] + d[mt][1];
                    acc[mt][1] += d[mt][2] + d[mt][3];
                }
            } else {
                int sid0 = __popc(tb & ((1u << (2 * c)) - 1));
                int sid1 = sid0 + ((tb >> (2 * c)) & 1);
#pragma unroll
                for (int mt = 0; mt < 4; mt++) {
                    acc[mt][0] += (sid0 == 0 ? d[mt][0] : 0.f) + (sid1 == 0 ? d[mt][1] : 0.f);
                    acc[mt][1] += (sid0 == 0 ? d[mt][2] : 0.f) + (sid1 == 0 ? d[mt][3] : 0.f);
                }
                seg_write(acc, acc_node, first && (nback == acc_node), out, c, r4);
                first = false;
                int last = __popc(tb);
                unsigned rem = tb;
                for (int s = 1; s <= last; s++) {
                    int pos = __ffs(rem) - 1;  rem &= rem - 1;
                    int node_s = __shfl_sync(0xffffffffu, nd, et * 8 + pos + 1);
                    if (s < last) {
                        float vv[4][2];
#pragma unroll
                        for (int mt = 0; mt < 4; mt++) {
                            vv[mt][0] = (sid0 == s ? d[mt][0] : 0.f) + (sid1 == s ? d[mt][1] : 0.f);
                            vv[mt][1] = (sid0 == s ? d[mt][2] : 0.f) + (sid1 == s ? d[mt][3] : 0.f);
                        }
                        seg_write(vv, node_s, false, out, c, r4);
                    } else {
#pragma unroll
                        for (int mt = 0; mt < 4; mt++) {
                            acc[mt][0] = (sid0 == s ? d[mt][0] : 0.f) + (sid1 == s ? d[mt][1] : 0.f);
                            acc[mt][1] = (sid0 == s ? d[mt][2] : 0.f) + (sid1 == s ? d[mt][3] : 0.f);
                        }
                        acc_node = node_s;
                    }
                }
            }
        }

        prev_last = __shfl_sync(0xffffffffu, nd, 15);
    }

    bool use_red = (first && (nback == acc_node)) || (nfwd == acc_node);
    seg_write(acc, acc_node, use_red, out, c, r4);
    CPWAIT(0);                                  // drain before exit
}

// ---------------- K5: epilogue scale out *= 1/den ----------------
__global__ void k_scale(float4* __restrict__ out4, int n4) {
    int i = blockIdx.x * blockDim.x + threadIdx.x;
    if (i >= n4) return;
    float s = g_invden[i >> 4];
    float4 v = out4[i];
    v.x *= s; v.y *= s; v.z *= s; v.w *= s;
    out4[i] = v;
}

// ---------------- launch ----------------
extern "C" void kernel_launch(void* const* d_in, const int* in_sizes, int n_in,
                              void* d_out, int out_size) {
    const float* emb = (const float*)d_in[0];   // [64,16]
    const float* cf  = (const float*)d_in[1];   // [E,16]
    const float* w   = (const float*)d_in[2];   // [E]
    const int*   idx = (const int*)d_in[3];     // [E]
    int E = in_sizes[2];
    float* out = (float*)d_out;                 // [100000,64]

    int eb = (E + 255) / 256;
    int n4 = out_size / 4;
    int Epad = ((E + 511) / 512) * 512;

    k_count<<<eb, 256>>>(idx, w, (float4*)d_out, n4, E);
    k_scan1<<<NB, SCAN_BS>>>();
    k_scatter<<<eb, 256>>>(idx, w, E, Epad);

    k_main<<<Epad / 512, 128>>>(emb, cf, out, E);
    k_scale<<<(n4 + 255) / 256, 256>>>((float4*)d_out, n4);
}

// round 13
// speedup vs baseline: 1.0535x; 1.0535x over previous
#include <cuda_runtime.h>
#include <stdint.h>

#define NODES   100000
#define MAX_E   3200000
#define SCAN_BS 1024
#define NB      ((NODES + SCAN_BS - 1) / SCAN_BS)   // 98
#define DEN_FX  16777216.0f
#define NWIN    16     // 16-edge windows per warp
#define PKS     8      // pack smem stages (ring)
#define GSS     4      // gather smem stages (ring)

// ---------------- scratch ----------------
__device__ unsigned long long g_cd[NODES];
__device__ int   g_cursor[NODES];
__device__ float g_invden[NODES];
__device__ int   g_bsum[NB];
__device__ uint4 g_pack[MAX_E + 1024];       // {eid, node, bits(w), 0}; padded w/ sentinels

// ---------------- helpers ----------------
__device__ __forceinline__ unsigned f2tf32(float f) {
    unsigned r;
    asm("cvt.rna.tf32.f32 %0, %1;" : "=r"(r) : "f"(f));
    return r;
}
__device__ __forceinline__ void mma_tf32(float& d0, float& d1, float& d2, float& d3,
                                         unsigned a0, unsigned a1, unsigned a2, unsigned a3,
                                         unsigned b0, unsigned b1) {
    asm volatile(
        "mma.sync.aligned.m16n8k8.row.col.f32.tf32.tf32.f32 "
        "{%0,%1,%2,%3}, {%4,%5,%6,%7}, {%8,%9}, {%0,%1,%2,%3};"
        : "+f"(d0), "+f"(d1), "+f"(d2), "+f"(d3)
        : "r"(a0), "r"(a1), "r"(a2), "r"(a3), "r"(b0), "r"(b1));
}
__device__ __forceinline__ void redadd(float* p, float v) {
    asm volatile("red.global.add.f32 [%0], %1;" :: "l"(p), "f"(v) : "memory");
}
__device__ __forceinline__ unsigned sptr(const void* p) {
    return (unsigned)__cvta_generic_to_shared(p);
}
#define CPA16(dst, src) asm volatile("cp.async.cg.shared.global [%0], [%1], 16;" :: "r"(dst), "l"(src))
#define CPCOMMIT()      asm volatile("cp.async.commit_group;" ::: "memory")
#define CPWAIT(n)       asm volatile("cp.async.wait_group %0;" :: "n"(n) : "memory")

// butterfly-sum over 4-lane group, lane c writes u-block mt==c. Skips sentinels.
__device__ __forceinline__ void seg_write(float a[4][2], int node, bool use_red,
                                          float* __restrict__ out, int c, int r4) {
#pragma unroll
    for (int mt = 0; mt < 4; mt++)
#pragma unroll
        for (int h = 0; h < 2; h++) {
            float v = a[mt][h];
            v += __shfl_xor_sync(0xffffffffu, v, 1);
            v += __shfl_xor_sync(0xffffffffu, v, 2);
            a[mt][h] = v;
        }
    if ((unsigned)node >= NODES) return;     // sentinel / invalid
    float vlo = (c == 0) ? a[0][0] : (c == 1) ? a[1][0] : (c == 2) ? a[2][0] : a[3][0];
    float vhi = (c == 0) ? a[0][1] : (c == 1) ? a[1][1] : (c == 2) ? a[2][1] : a[3][1];
    float* dst = out + (size_t)node * 64 + c * 16 + r4;
    if (use_red) { redadd(dst, vlo); redadd(dst + 8, vhi); }
    else         { dst[0] = vlo; dst[8] = vhi; }
}

// ---------------- K1: count + weight-sum + zero out[] ----------------
__global__ void k_count(const int* __restrict__ idx, const float* __restrict__ w,
                        float4* __restrict__ out4, int n4, int E) {
    int e = blockIdx.x * blockDim.x + threadIdx.x;
    for (int z = e; z < n4; z += gridDim.x * blockDim.x)
        out4[z] = make_float4(0.f, 0.f, 0.f, 0.f);
    if (e >= E) return;
    int n = idx[e];
    unsigned fx = __float2uint_rn(w[e] * DEN_FX);
    atomicAdd(&g_cd[n], (1ULL << 32) | (unsigned long long)fx);
}

// ---------------- K2: block-local scan + invden + g_cd re-zero ----------------
__global__ void k_scan1() {
    __shared__ int wsum[32];
    int t = threadIdx.x, b = blockIdx.x;
    int i = b * SCAN_BS + t;
    int lane = t & 31, wq = t >> 5;
    unsigned long long cd = (i < NODES) ? g_cd[i] : 0ULL;
    int v = (int)(cd >> 32);
    if (i < NODES) {
        g_cd[i] = 0ULL;
        g_invden[i] = __fdividef(DEN_FX, (float)(unsigned)(cd & 0xffffffffULL));
    }
    int x = v;
#pragma unroll
    for (int d = 1; d < 32; d <<= 1) {
        int y = __shfl_up_sync(0xffffffffu, x, d);
        if (lane >= d) x += y;
    }
    if (lane == 31) wsum[wq] = x;
    __syncthreads();
    if (wq == 0) {
        int s = wsum[lane];
#pragma unroll
        for (int d = 1; d < 32; d <<= 1) {
            int y = __shfl_up_sync(0xffffffffu, s, d);
            if (lane >= d) s += y;
        }
        wsum[lane] = s;
    }
    __syncthreads();
    int base = wq ? wsum[wq - 1] : 0;
    if (i < NODES) g_cursor[i] = base + x - v;
    if (t == 0) g_bsum[b] = wsum[31];
}

// ---------------- K3: scatter (inline bsum prefix) + sentinel padding ----------------
__global__ void k_scatter(const int* __restrict__ idx, const float* __restrict__ w,
                          int E, int Epad) {
    __shared__ int s_boff[128];
    __shared__ int s_wt[4];
    int t = threadIdx.x;
    int lane = t & 31, wq = t >> 5;
    int v = 0, x = 0;
    if (t < 128) {
        v = (t < NB) ? g_bsum[t] : 0;
        x = v;
#pragma unroll
        for (int d = 1; d < 32; d <<= 1) {
            int y = __shfl_up_sync(0xffffffffu, x, d);
            if (lane >= d) x += y;
        }
        if (lane == 31) s_wt[wq] = x;
    }
    __syncthreads();
    if (t < 128) {
        int addv = 0;
#pragma unroll
        for (int k = 0; k < 4; k++) if (k < wq) addv += s_wt[k];
        s_boff[t] = addv + x - v;
    }
    __syncthreads();
    int e = blockIdx.x * blockDim.x + t;
    if (e < Epad - E)                                    // sentinel tail
        g_pack[E + e] = make_uint4(0u, (unsigned)NODES, 0u, 0u);
    if (e >= E) return;
    int n = idx[e];
    int p = atomicAdd(&g_cursor[n], 1) + s_boff[n >> 10];
    g_pack[p] = make_uint4((unsigned)e, (unsigned)n, __float_as_uint(w[e]), 0u);
}

// ---------------- K4: cp.async-pipelined transposed MMA + register seg reduce ----------------
__global__ void __launch_bounds__(128, 6)
k_main(const float* __restrict__ emb, const float* __restrict__ cf,
       float* __restrict__ out, int E) {
    __shared__ __align__(16) uint4 s_pk[4][PKS][16];      // 8 KB
    __shared__ __align__(16) float s_gb[4][GSS][256];     // 16 KB

    int t = threadIdx.x, wp = t >> 5, l = t & 31;
    int c = l & 3, r4 = l >> 2;
    int wb = (blockIdx.x * 4 + wp) * (NWIN * 16);

    // --- A fragments, K-permuted (slot c holds k=4c+j, matching quarter-major B).
    //     A keeps cvt.rna (amortized); B uses raw-f32 truncation in the hot loop
    //     (tf32 MMA reads operand bits[31:13]) to avoid per-window CVTs. ---
    unsigned A[4][2][4];
#pragma unroll
    for (int mt = 0; mt < 4; mt++)
#pragma unroll
        for (int kt = 0; kt < 2; kt++) {
            const float* p = emb + (mt * 16 + r4) * 16 + 4 * c + 2 * kt;
            A[mt][kt][0] = f2tf32(__ldg(p));
            A[mt][kt][1] = f2tf32(__ldg(p + 128));
            A[mt][kt][2] = f2tf32(__ldg(p + 1));
            A[mt][kt][3] = f2tf32(__ldg(p + 129));
        }

    int nback = -2, nfwd = -2;
    if (wb > 0)              nback = (int)__ldg(&g_pack[wb - 1]).y;
    if (wb + NWIN * 16 < E)  nfwd  = (int)__ldg(&g_pack[wb + NWIN * 16]).y;

    // --- prologue: packs for windows 0..6 (ring fill), then gathers 0..2 ---
    for (int i = l; i < 112; i += 32)
        CPA16(sptr(&s_pk[wp][i >> 4][i & 15]), g_pack + wb + i);
    CPCOMMIT();
    CPWAIT(0); __syncwarp();
#pragma unroll
    for (int g = 0; g < 3; g++) {
#pragma unroll
        for (int h = 0; h < 2; h++) {
            int i = l + h * 32;
            unsigned eid = s_pk[wp][g][i >> 2].x;
            CPA16(sptr(&s_gb[wp][g][i * 4]), cf + (size_t)eid * 16 + (i & 3) * 4);
        }
        CPCOMMIT();
    }

    float acc[4][2];
#pragma unroll
    for (int mt = 0; mt < 4; mt++) { acc[mt][0] = 0.f; acc[mt][1] = 0.f; }
    int acc_node = -1;
    bool first = true;
    int prev_last = 0;

#pragma unroll 1
    for (int j = 0; j < NWIN; j++) {
        CPWAIT(2); __syncwarp();               // gather j + packs through j+4 resident

        uint4* pkw = s_pk[wp][j & 7];
        int   nd = (int)pkw[l & 15].y;
        float w0 = __uint_as_float(pkw[r4].z);
        float w1 = __uint_as_float(pkw[8 + r4].z);
        int ndn = __shfl_down_sync(0xffffffffu, nd, 1);
        unsigned bm = __ballot_sync(0xffffffffu, (l < 15) && (nd != ndn)) & 0x7fffu;
        int node0 = __shfl_sync(0xffffffffu, nd, 0);

        // --- issue next loads (hidden under this window's compute) ---
        if (j + 3 < NWIN) {
            uint4* pks = s_pk[wp][(j + 3) & 7];
#pragma unroll
            for (int h = 0; h < 2; h++) {
                int i = l + h * 32;
                unsigned eid = pks[i >> 2].x;
                CPA16(sptr(&s_gb[wp][(j + 3) & 3][i * 4]), cf + (size_t)eid * 16 + (i & 3) * 4);
            }
        }
        if (j + 7 < NWIN) {
            if (l < 16)
                CPA16(sptr(&s_pk[wp][(j + 7) & 7][l]), g_pack + wb + (j + 7) * 16 + l);
        }
        CPCOMMIT();

        // --- B values from smem (quarter-major, conflict-free) ---
        const float* gw = s_gb[wp][j & 3];
        float4 B0 = *(const float4*)(gw + r4 * 16 + 4 * c);
        float4 B1 = *(const float4*)(gw + (8 + r4) * 16 + 4 * c);

        if (j == 0) acc_node = node0;
        else if (prev_last != node0) {
            seg_write(acc, acc_node, first && (nback == acc_node), out, c, r4);
            first = false;
#pragma unroll
            for (int mt = 0; mt < 4; mt++) { acc[mt][0] = 0.f; acc[mt][1] = 0.f; }
            acc_node = node0;
        }

#pragma unroll
        for (int et = 0; et < 2; et++) {
            if (et == 1 && (bm & 0x0080u)) {   // seam between edge 7 and 8
                seg_write(acc, acc_node, first && (nback == acc_node), out, c, r4);
                first = false;
#pragma unroll
                for (int mt = 0; mt < 4; mt++) { acc[mt][0] = 0.f; acc[mt][1] = 0.f; }
                acc_node = __shfl_sync(0xffffffffu, nd, 8);
            }

            float wv = et ? w1 : w0;
            float4 Bv = et ? B1 : B0;
            // raw f32 bits as tf32 (truncation) — no CVT in the hot loop
            unsigned b0 = __float_as_uint(Bv.x * wv);
            unsigned b1 = __float_as_uint(Bv.y * wv);
            unsigned b2 = __float_as_uint(Bv.z * wv);
            unsigned b3 = __float_as_uint(Bv.w * wv);

            float d[4][4];
#pragma unroll
            for (int mt = 0; mt < 4; mt++) {
                d[mt][0] = 0.f; d[mt][1] = 0.f; d[mt][2] = 0.f; d[mt][3] = 0.f;
                mma_tf32(d[mt][0], d[mt][1], d[mt][2], d[mt][3],
                         A[mt][0][0], A[mt][0][1], A[mt][0][2], A[mt][0][3], b0, b1);
                mma_tf32(d[mt][0], d[mt][1], d[mt][2], d[mt][3],
                         A[mt][1][0], A[mt][1][1], A[mt][1][2], A[mt][1][3], b2, b3);
                d[mt][0] = fmaxf(d[mt][0], 0.f);
                d[mt][1] = fmaxf(d[mt][1], 0.f);
                d[mt][2] = fmaxf(d[mt][2], 0.f);
                d[mt][3] = fmaxf(d[mt][3], 0.f);
            }

            unsigned tb = (bm >> (et * 8)) & 0x7fu;
            if (tb == 0) {
#pragma unroll
                for (int mt = 0; mt < 4; mt++) {
                    acc[mt][0] += d[mt][0] + d[mt][1];
                    acc[mt][1] += d[mt][2] + d[mt][3];
                }
            } else {
                int sid0 = __popc(tb & ((1u << (2 * c)) - 1));
                int sid1 = sid0 + ((tb >> (2 * c)) & 1);
#pragma unroll
                for (int mt = 0; mt < 4; mt++) {
                    acc[mt][0] += (sid0 == 0 ? d[mt][0] : 0.f) + (sid1 == 0 ? d[mt][1] : 0.f);
                    acc[mt][1] += (sid0 == 0 ? d[mt][2] : 0.f) + (sid1 == 0 ? d[mt][3] : 0.f);
                }
                seg_write(acc, acc_node, first && (nback == acc_node), out, c, r4);
                first = false;
                int last = __popc(tb);
                unsigned rem = tb;
                for (int s = 1; s <= last; s++) {
                    int pos = __ffs(rem) - 1;  rem &= rem - 1;
                    int node_s = __shfl_sync(0xffffffffu, nd, et * 8 + pos + 1);
                    if (s < last) {
                        float vv[4][2];
#pragma unroll
                        for (int mt = 0; mt < 4; mt++) {
                            vv[mt][0] = (sid0 == s ? d[mt][0] : 0.f) + (sid1 == s ? d[mt][1] : 0.f);
                            vv[mt][1] = (sid0 == s ? d[mt][2] : 0.f) + (sid1 == s ? d[mt][3] : 0.f);
                        }
                        seg_write(vv, node_s, false, out, c, r4);
                    } else {
#pragma unroll
                        for (int mt = 0; mt < 4; mt++) {
                            acc[mt][0] = (sid0 == s ? d[mt][0] : 0.f) + (sid1 == s ? d[mt][1] : 0.f);
                            acc[mt][1] = (sid0 == s ? d[mt][2] : 0.f) + (sid1 == s ? d[mt][3] : 0.f);
                        }
                        acc_node = node_s;
                    }
                }
            }
        }

        prev_last = __shfl_sync(0xffffffffu, nd, 15);
    }

    bool use_red = (first && (nback == acc_node)) || (nfwd == acc_node);
    seg_write(acc, acc_node, use_red, out, c, r4);
    CPWAIT(0);                                  // drain before exit
}

// ---------------- K5: epilogue scale out *= 1/den ----------------
__global__ void k_scale(float4* __restrict__ out4, int n4) {
    int i = blockIdx.x * blockDim.x + threadIdx.x;
    if (i >= n4) return;
    float s = g_invden[i >> 4];
    float4 v = out4[i];
    v.x *= s; v.y *= s; v.z *= s; v.w *= s;
    out4[i] = v;
}

// ---------------- launch ----------------
extern "C" void kernel_launch(void* const* d_in, const int* in_sizes, int n_in,
                              void* d_out, int out_size) {
    const float* emb = (const float*)d_in[0];   // [64,16]
    const float* cf  = (const float*)d_in[1];   // [E,16]
    const float* w   = (const float*)d_in[2];   // [E]
    const int*   idx = (const int*)d_in[3];     // [E]
    int E = in_sizes[2];
    float* out = (float*)d_out;                 // [100000,64]

    int eb = (E + 255) / 256;
    int n4 = out_size / 4;
    int Epad = ((E + 1023) / 1024) * 1024;      // 4 warps x NWIN*16 = 1024 edges/block

    k_count<<<eb, 256>>>(idx, w, (float4*)d_out, n4, E);
    k_scan1<<<NB, SCAN_BS>>>();
    k_scatter<<<eb, 256>>>(idx, w, E, Epad);

    k_main<<<Epad / 1024, 128>>>(emb, cf, out, E);
    k_scale<<<(n4 + 255) / 256, 256>>>((float4*)d_out, n4);
}

// round 14
// speedup vs baseline: 1.0663x; 1.0122x over previous
#include <cuda_runtime.h>
#include <stdint.h>

#define NODES   100000
#define MAX_E   3200000
#define SCAN_BS 1024
#define NB      ((NODES + SCAN_BS - 1) / SCAN_BS)   // 98
#define DEN_FX  16777216.0f
#define NW2     8      // 32-edge windows per warp (256 edges/warp)
#define PKS     4      // pack ring stages (32 entries each)
#define GSS     3      // gather ring stages (2KB each)

// ---------------- scratch ----------------
__device__ unsigned long long g_cd[NODES];
__device__ int   g_cursor[NODES];
__device__ float g_invden[NODES];
__device__ int   g_bsum[NB];
__device__ uint4 g_pack[MAX_E + 1024];       // {eid, node, bits(w), 0}; sentinel-padded

// ---------------- helpers ----------------
__device__ __forceinline__ unsigned f2tf32(float f) {
    unsigned r;
    asm("cvt.rna.tf32.f32 %0, %1;" : "=r"(r) : "f"(f));
    return r;
}
__device__ __forceinline__ void mma_tf32(float& d0, float& d1, float& d2, float& d3,
                                         unsigned a0, unsigned a1, unsigned a2, unsigned a3,
                                         unsigned b0, unsigned b1) {
    asm volatile(
        "mma.sync.aligned.m16n8k8.row.col.f32.tf32.tf32.f32 "
        "{%0,%1,%2,%3}, {%4,%5,%6,%7}, {%8,%9}, {%0,%1,%2,%3};"
        : "+f"(d0), "+f"(d1), "+f"(d2), "+f"(d3)
        : "r"(a0), "r"(a1), "r"(a2), "r"(a3), "r"(b0), "r"(b1));
}
__device__ __forceinline__ void redadd(float* p, float v) {
    asm volatile("red.global.add.f32 [%0], %1;" :: "l"(p), "f"(v) : "memory");
}
__device__ __forceinline__ unsigned sptr(const void* p) {
    return (unsigned)__cvta_generic_to_shared(p);
}
#define CPA16(dst, src) asm volatile("cp.async.cg.shared.global [%0], [%1], 16;" :: "r"(dst), "l"(src))
#define CPCOMMIT()      asm volatile("cp.async.commit_group;" ::: "memory")
#define CPWAIT(n)       asm volatile("cp.async.wait_group %0;" :: "n"(n) : "memory")

// butterfly-sum over 4-lane group, lane c writes u-block mt==c. Skips sentinels.
__device__ __forceinline__ void seg_write(float a[4][2], int node, bool use_red,
                                          float* __restrict__ out, int c, int r4) {
#pragma unroll
    for (int mt = 0; mt < 4; mt++)
#pragma unroll
        for (int h = 0; h < 2; h++) {
            float v = a[mt][h];
            v += __shfl_xor_sync(0xffffffffu, v, 1);
            v += __shfl_xor_sync(0xffffffffu, v, 2);
            a[mt][h] = v;
        }
    if ((unsigned)node >= NODES) return;     // sentinel / invalid
    float vlo = (c == 0) ? a[0][0] : (c == 1) ? a[1][0] : (c == 2) ? a[2][0] : a[3][0];
    float vhi = (c == 0) ? a[0][1] : (c == 1) ? a[1][1] : (c == 2) ? a[2][1] : a[3][1];
    float* dst = out + (size_t)node * 64 + c * 16 + r4;
    if (use_red) { redadd(dst, vlo); redadd(dst + 8, vhi); }
    else         { dst[0] = vlo; dst[8] = vhi; }
}

// ---------------- K1: count + weight-sum + zero out[] (4 edges/thread) ----------------
__global__ void k_count(const int* __restrict__ idx, const float* __restrict__ w,
                        float4* __restrict__ out4, int n4, int E) {
    int i = blockIdx.x * blockDim.x + threadIdx.x;
    for (int z = i; z < n4; z += gridDim.x * blockDim.x)
        out4[z] = make_float4(0.f, 0.f, 0.f, 0.f);
    int e = i * 4;
    if (e + 3 < E) {
        int4   nv = *(const int4*)(idx + e);
        float4 wv = *(const float4*)(w + e);
        atomicAdd(&g_cd[nv.x], (1ULL << 32) | (unsigned long long)__float2uint_rn(wv.x * DEN_FX));
        atomicAdd(&g_cd[nv.y], (1ULL << 32) | (unsigned long long)__float2uint_rn(wv.y * DEN_FX));
        atomicAdd(&g_cd[nv.z], (1ULL << 32) | (unsigned long long)__float2uint_rn(wv.z * DEN_FX));
        atomicAdd(&g_cd[nv.w], (1ULL << 32) | (unsigned long long)__float2uint_rn(wv.w * DEN_FX));
    } else {
        for (int k = e; k < E; k++)
            atomicAdd(&g_cd[idx[k]],
                      (1ULL << 32) | (unsigned long long)__float2uint_rn(w[k] * DEN_FX));
    }
}

// ---------------- K2: block-local scan + invden + g_cd re-zero ----------------
__global__ void k_scan1() {
    __shared__ int wsum[32];
    int t = threadIdx.x, b = blockIdx.x;
    int i = b * SCAN_BS + t;
    int lane = t & 31, wq = t >> 5;
    unsigned long long cd = (i < NODES) ? g_cd[i] : 0ULL;
    int v = (int)(cd >> 32);
    if (i < NODES) {
        g_cd[i] = 0ULL;
        g_invden[i] = __fdividef(DEN_FX, (float)(unsigned)(cd & 0xffffffffULL));
    }
    int x = v;
#pragma unroll
    for (int d = 1; d < 32; d <<= 1) {
        int y = __shfl_up_sync(0xffffffffu, x, d);
        if (lane >= d) x += y;
    }
    if (lane == 31) wsum[wq] = x;
    __syncthreads();
    if (wq == 0) {
        int s = wsum[lane];
#pragma unroll
        for (int d = 1; d < 32; d <<= 1) {
            int y = __shfl_up_sync(0xffffffffu, s, d);
            if (lane >= d) s += y;
        }
        wsum[lane] = s;
    }
    __syncthreads();
    int base = wq ? wsum[wq - 1] : 0;
    if (i < NODES) g_cursor[i] = base + x - v;
    if (t == 0) g_bsum[b] = wsum[31];
}

// ---------------- K3: scatter (inline bsum prefix, 2 edges/thread) + sentinels ----------------
__global__ void k_scatter(const int* __restrict__ idx, const float* __restrict__ w,
                          int E, int Epad) {
    __shared__ int s_boff[128];
    __shared__ int s_wt[4];
    int t = threadIdx.x;
    int lane = t & 31, wq = t >> 5;
    int v = 0, x = 0;
    if (t < 128) {
        v = (t < NB) ? g_bsum[t] : 0;
        x = v;
#pragma unroll
        for (int d = 1; d < 32; d <<= 1) {
            int y = __shfl_up_sync(0xffffffffu, x, d);
            if (lane >= d) x += y;
        }
        if (lane == 31) s_wt[wq] = x;
    }
    __syncthreads();
    if (t < 128) {
        int addv = 0;
#pragma unroll
        for (int k = 0; k < 4; k++) if (k < wq) addv += s_wt[k];
        s_boff[t] = addv + x - v;
    }
    __syncthreads();
    int i = blockIdx.x * blockDim.x + t;
    if (i < Epad - E)                                    // sentinel tail (<=1023 entries)
        g_pack[E + i] = make_uint4(0u, (unsigned)NODES, 0u, 0u);
    int e = i * 2;
    if (e + 1 < E) {
        int2   nn = *(const int2*)(idx + e);
        float2 ww = *(const float2*)(w + e);
        int p0 = atomicAdd(&g_cursor[nn.x], 1) + s_boff[nn.x >> 10];
        g_pack[p0] = make_uint4((unsigned)e, (unsigned)nn.x, __float_as_uint(ww.x), 0u);
        int p1 = atomicAdd(&g_cursor[nn.y], 1) + s_boff[nn.y >> 10];
        g_pack[p1] = make_uint4((unsigned)(e + 1), (unsigned)nn.y, __float_as_uint(ww.y), 0u);
    } else if (e < E) {
        int n = idx[e];
        int p = atomicAdd(&g_cursor[n], 1) + s_boff[n >> 10];
        g_pack[p] = make_uint4((unsigned)e, (unsigned)n, __float_as_uint(w[e]), 0u);
    }
}

// ---------------- K4: cp.async-pipelined transposed MMA, 32-edge windows ----------------
__global__ void __launch_bounds__(128, 6)
k_main(const float* __restrict__ emb, const float* __restrict__ cf,
       float* __restrict__ out, int E) {
    __shared__ __align__(16) uint4 s_pk[4][PKS][32];      // 8 KB
    __shared__ __align__(16) float s_gb[4][GSS][512];     // 24 KB

    int t = threadIdx.x, wp = t >> 5, l = t & 31;
    int c = l & 3, r4 = l >> 2;
    int wb = (blockIdx.x * 4 + wp) * (NW2 * 32);

    // --- A fragments, K-permuted (slot c holds k=4c+j, matching quarter-major B).
    //     A keeps cvt.rna (amortized); B uses raw-f32 truncation in the hot loop. ---
    unsigned A[4][2][4];
#pragma unroll
    for (int mt = 0; mt < 4; mt++)
#pragma unroll
        for (int kt = 0; kt < 2; kt++) {
            const float* p = emb + (mt * 16 + r4) * 16 + 4 * c + 2 * kt;
            A[mt][kt][0] = f2tf32(__ldg(p));
            A[mt][kt][1] = f2tf32(__ldg(p + 128));
            A[mt][kt][2] = f2tf32(__ldg(p + 1));
            A[mt][kt][3] = f2tf32(__ldg(p + 129));
        }

    int nback = -2, nfwd = -2;
    if (wb > 0)              nback = (int)__ldg(&g_pack[wb - 1]).y;
    if (wb + NW2 * 32 < E)   nfwd  = (int)__ldg(&g_pack[wb + NW2 * 32]).y;

    // --- prologue: packs for windows 0..3 (full ring), then gathers 0,1 ---
#pragma unroll
    for (int h = 0; h < 4; h++) {
        int i = l + h * 32;
        CPA16(sptr(&s_pk[wp][i >> 5][i & 31]), g_pack + wb + i);
    }
    CPCOMMIT();
    CPWAIT(0); __syncwarp();
#pragma unroll
    for (int g = 0; g < 2; g++) {
#pragma unroll
        for (int h = 0; h < 4; h++) {
            int i = l + h * 32;
            unsigned eid = s_pk[wp][g][i >> 2].x;
            CPA16(sptr(&s_gb[wp][g][i * 4]), cf + (size_t)eid * 16 + (i & 3) * 4);
        }
        CPCOMMIT();
    }

    float acc[4][2];
#pragma unroll
    for (int mt = 0; mt < 4; mt++) { acc[mt][0] = 0.f; acc[mt][1] = 0.f; }
    int acc_node = -1;
    bool first = true;
    int prev_last = 0;

#pragma unroll 1
    for (int j = 0; j < NW2; j++) {
        // Group(j-2) = {gather j, pack j+2} completes here; Group(j-1) may pend.
        CPWAIT(1); __syncwarp();

        uint4 pk = s_pk[wp][j & 3][l];         // lane l = edge l of this 32-edge window
        int   nd = (int)pk.y;
        float wreg = __uint_as_float(pk.z);
        int ndn = __shfl_down_sync(0xffffffffu, nd, 1);
        unsigned bm = __ballot_sync(0xffffffffu, (l < 31) && (nd != ndn)) & 0x7fffffffu;
        int node0 = __shfl_sync(0xffffffffu, nd, 0);

        // --- Group(j): gather j+2 (pack j+2 resident) + pack j+4 ---
        if (j + 2 < NW2) {
            int st = (j + 2) % GSS;
            uint4* pks = s_pk[wp][(j + 2) & 3];
#pragma unroll
            for (int h = 0; h < 4; h++) {
                int i = l + h * 32;
                unsigned eid = pks[i >> 2].x;
                CPA16(sptr(&s_gb[wp][st][i * 4]), cf + (size_t)eid * 16 + (i & 3) * 4);
            }
        }
        if (j + 4 < NW2)
            CPA16(sptr(&s_pk[wp][(j + 4) & 3][l]), g_pack + wb + (j + 4) * 32 + l);
        CPCOMMIT();

        const float* gw = s_gb[wp][j % GSS];

        if (j == 0) acc_node = node0;
        else if (prev_last != node0) {
            seg_write(acc, acc_node, first && (nback == acc_node), out, c, r4);
            first = false;
#pragma unroll
            for (int mt = 0; mt < 4; mt++) { acc[mt][0] = 0.f; acc[mt][1] = 0.f; }
            acc_node = node0;
        }

#pragma unroll
        for (int et = 0; et < 4; et++) {
            if (et > 0 && (bm & (1u << (et * 8 - 1)))) {   // seam before this tile
                seg_write(acc, acc_node, first && (nback == acc_node), out, c, r4);
                first = false;
#pragma unroll
                for (int mt = 0; mt < 4; mt++) { acc[mt][0] = 0.f; acc[mt][1] = 0.f; }
                acc_node = __shfl_sync(0xffffffffu, nd, et * 8);
            }

            float wv = __shfl_sync(0xffffffffu, wreg, et * 8 + r4);
            float4 Bv = *(const float4*)(gw + (et * 8 + r4) * 16 + 4 * c);
            unsigned b0 = __float_as_uint(Bv.x * wv);
            unsigned b1 = __float_as_uint(Bv.y * wv);
            unsigned b2 = __float_as_uint(Bv.z * wv);
            unsigned b3 = __float_as_uint(Bv.w * wv);

            float d[4][4];
#pragma unroll
            for (int mt = 0; mt < 4; mt++) {
                d[mt][0] = 0.f; d[mt][1] = 0.f; d[mt][2] = 0.f; d[mt][3] = 0.f;
                mma_tf32(d[mt][0], d[mt][1], d[mt][2], d[mt][3],
                         A[mt][0][0], A[mt][0][1], A[mt][0][2], A[mt][0][3], b0, b1);
                mma_tf32(d[mt][0], d[mt][1], d[mt][2], d[mt][3],
                         A[mt][1][0], A[mt][1][1], A[mt][1][2], A[mt][1][3], b2, b3);
                d[mt][0] = fmaxf(d[mt][0], 0.f);
                d[mt][1] = fmaxf(d[mt][1], 0.f);
                d[mt][2] = fmaxf(d[mt][2], 0.f);
                d[mt][3] = fmaxf(d[mt][3], 0.f);
            }

            unsigned tb = (bm >> (et * 8)) & 0x7fu;        // intra-tile boundaries
            if (tb == 0) {
#pragma unroll
                for (int mt = 0; mt < 4; mt++) {
                    acc[mt][0] += d[mt][0] + d[mt][1];
                    acc[mt][1] += d[mt][2] + d[mt][3];
                }
            } else {
                int sid0 = __popc(tb & ((1u << (2 * c)) - 1));
                int sid1 = sid0 + ((tb >> (2 * c)) & 1);
#pragma unroll
                for (int mt = 0; mt < 4; mt++) {
                    acc[mt][0] += (sid0 == 0 ? d[mt][0] : 0.f) + (sid1 == 0 ? d[mt][1] : 0.f);
                    acc[mt][1] += (sid0 == 0 ? d[mt][2] : 0.f) + (sid1 == 0 ? d[mt][3] : 0.f);
                }
                seg_write(acc, acc_node, first && (nback == acc_node), out, c, r4);
                first = false;
                int last = __popc(tb);
                unsigned rem = tb;
                for (int s = 1; s <= last; s++) {
                    int pos = __ffs(rem) - 1;  rem &= rem - 1;
                    int node_s = __shfl_sync(0xffffffffu, nd, et * 8 + pos + 1);
                    if (s < last) {
                        float vv[4][2];
#pragma unroll
                        for (int mt = 0; mt < 4; mt++) {
                            vv[mt][0] = (sid0 == s ? d[mt][0] : 0.f) + (sid1 == s ? d[mt][1] : 0.f);
                            vv[mt][1] = (sid0 == s ? d[mt][2] : 0.f) + (sid1 == s ? d[mt][3] : 0.f);
                        }
                        seg_write(vv, node_s, false, out, c, r4);
                    } else {
#pragma unroll
                        for (int mt = 0; mt < 4; mt++) {
                            acc[mt][0] = (sid0 == s ? d[mt][0] : 0.f) + (sid1 == s ? d[mt][1] : 0.f);
                            acc[mt][1] = (sid0 == s ? d[mt][2] : 0.f) + (sid1 == s ? d[mt][3] : 0.f);
                        }
                        acc_node = node_s;
                    }
                }
            }
        }

        prev_last = __shfl_sync(0xffffffffu, nd, 31);
    }

    bool use_red = (first && (nback == acc_node)) || (nfwd == acc_node);
    seg_write(acc, acc_node, use_red, out, c, r4);
    CPWAIT(0);                                  // drain before exit
}

// ---------------- K5: epilogue scale out *= 1/den ----------------
__global__ void k_scale(float4* __restrict__ out4, int n4) {
    int i = blockIdx.x * blockDim.x + threadIdx.x;
    if (i >= n4) return;
    float s = g_invden[i >> 4];
    float4 v = out4[i];
    v.x *= s; v.y *= s; v.z *= s; v.w *= s;
    out4[i] = v;
}

// ---------------- launch ----------------
extern "C" void kernel_launch(void* const* d_in, const int* in_sizes, int n_in,
                              void* d_out, int out_size) {
    const float* emb = (const float*)d_in[0];   // [64,16]
    const float* cf  = (const float*)d_in[1];   // [E,16]
    const float* w   = (const float*)d_in[2];   // [E]
    const int*   idx = (const int*)d_in[3];     // [E]
    int E = in_sizes[2];
    float* out = (float*)d_out;                 // [100000,64]

    int n4 = out_size / 4;
    int Epad = ((E + 1023) / 1024) * 1024;      // 4 warps x 256 edges per block
    int e4b = ((E + 3) / 4 + 255) / 256;
    int e2b = ((E + 1) / 2 + 255) / 256;

    k_count<<<e4b, 256>>>(idx, w, (float4*)d_out, n4, E);
    k_scan1<<<NB, SCAN_BS>>>();
    k_scatter<<<e2b, 256>>>(idx, w, E, Epad);

    k_main<<<Epad / 1024, 128>>>(emb, cf, out, E);
    k_scale<<<(n4 + 255) / 256, 256>>>((float4*)d_out, n4);
}

// round 15
// speedup vs baseline: 1.0928x; 1.0248x over previous
#include <cuda_runtime.h>
#include <stdint.h>

#define NODES   100000
#define MAX_E   3200000
#define SCAN_BS 1024
#define NB      ((NODES + SCAN_BS - 1) / SCAN_BS)   // 98
#define DEN_FX  16777216.0f
#define NW2     8      // 32-edge windows per warp (256 edges/warp)
#define PKS     4      // pack ring stages (32 entries each)
#define GSS     3      // gather ring stages (2KB each)

// ---------------- scratch ----------------
__device__ unsigned long long g_cd[NODES];
__device__ int   g_cursor[NODES];
__device__ float g_invden[NODES];
__device__ int   g_bsum[NB];
__device__ uint4 g_pack[MAX_E + 1024];       // {eid, node, bits(w), 0}; sentinel-padded

// ---------------- helpers ----------------
__device__ __forceinline__ unsigned f2tf32(float f) {
    unsigned r;
    asm("cvt.rna.tf32.f32 %0, %1;" : "=r"(r) : "f"(f));
    return r;
}
__device__ __forceinline__ void mma_tf32(float& d0, float& d1, float& d2, float& d3,
                                         unsigned a0, unsigned a1, unsigned a2, unsigned a3,
                                         unsigned b0, unsigned b1) {
    asm volatile(
        "mma.sync.aligned.m16n8k8.row.col.f32.tf32.tf32.f32 "
        "{%0,%1,%2,%3}, {%4,%5,%6,%7}, {%8,%9}, {%0,%1,%2,%3};"
        : "+f"(d0), "+f"(d1), "+f"(d2), "+f"(d3)
        : "r"(a0), "r"(a1), "r"(a2), "r"(a3), "r"(b0), "r"(b1));
}
__device__ __forceinline__ void redadd(float* p, float v) {
    asm volatile("red.global.add.f32 [%0], %1;" :: "l"(p), "f"(v) : "memory");
}
__device__ __forceinline__ unsigned sptr(const void* p) {
    return (unsigned)__cvta_generic_to_shared(p);
}
#define CPA16(dst, src) asm volatile("cp.async.cg.shared.global [%0], [%1], 16;" :: "r"(dst), "l"(src))
#define CPCOMMIT()      asm volatile("cp.async.commit_group;" ::: "memory")
#define CPWAIT(n)       asm volatile("cp.async.wait_group %0;" :: "n"(n) : "memory")

// butterfly-sum over 4-lane group, scale by 1/den, lane c writes u-block mt==c.
__device__ __forceinline__ void seg_write(float a[4][2], int node, bool use_red,
                                          float* __restrict__ out, int c, int r4) {
#pragma unroll
    for (int mt = 0; mt < 4; mt++)
#pragma unroll
        for (int h = 0; h < 2; h++) {
            float v = a[mt][h];
            v += __shfl_xor_sync(0xffffffffu, v, 1);
            v += __shfl_xor_sync(0xffffffffu, v, 2);
            a[mt][h] = v;
        }
    if ((unsigned)node >= NODES) return;     // sentinel / invalid
    float s = __ldg(&g_invden[node]);        // broadcast (all lanes same addr)
    float vlo = (c == 0) ? a[0][0] : (c == 1) ? a[1][0] : (c == 2) ? a[2][0] : a[3][0];
    float vhi = (c == 0) ? a[0][1] : (c == 1) ? a[1][1] : (c == 2) ? a[2][1] : a[3][1];
    vlo *= s; vhi *= s;                      // distributes over red-add partials
    float* dst = out + (size_t)node * 64 + c * 16 + r4;
    if (use_red) { redadd(dst, vlo); redadd(dst + 8, vhi); }
    else         { dst[0] = vlo; dst[8] = vhi; }
}

// ---------------- K1: count + weight-sum + zero out[] (4 edges/thread) ----------------
__global__ void k_count(const int* __restrict__ idx, const float* __restrict__ w,
                        float4* __restrict__ out4, int n4, int E) {
    int i = blockIdx.x * blockDim.x + threadIdx.x;
    for (int z = i; z < n4; z += gridDim.x * blockDim.x)
        out4[z] = make_float4(0.f, 0.f, 0.f, 0.f);
    int e = i * 4;
    if (e + 3 < E) {
        int4   nv = *(const int4*)(idx + e);
        float4 wv = *(const float4*)(w + e);
        atomicAdd(&g_cd[nv.x], (1ULL << 32) | (unsigned long long)__float2uint_rn(wv.x * DEN_FX));
        atomicAdd(&g_cd[nv.y], (1ULL << 32) | (unsigned long long)__float2uint_rn(wv.y * DEN_FX));
        atomicAdd(&g_cd[nv.z], (1ULL << 32) | (unsigned long long)__float2uint_rn(wv.z * DEN_FX));
        atomicAdd(&g_cd[nv.w], (1ULL << 32) | (unsigned long long)__float2uint_rn(wv.w * DEN_FX));
    } else {
        for (int k = e; k < E; k++)
            atomicAdd(&g_cd[idx[k]],
                      (1ULL << 32) | (unsigned long long)__float2uint_rn(w[k] * DEN_FX));
    }
}

// ---------------- K2: block-local scan + invden + g_cd re-zero ----------------
__global__ void k_scan1() {
    __shared__ int wsum[32];
    int t = threadIdx.x, b = blockIdx.x;
    int i = b * SCAN_BS + t;
    int lane = t & 31, wq = t >> 5;
    unsigned long long cd = (i < NODES) ? g_cd[i] : 0ULL;
    int v = (int)(cd >> 32);
    if (i < NODES) {
        g_cd[i] = 0ULL;
        g_invden[i] = __fdividef(DEN_FX, (float)(unsigned)(cd & 0xffffffffULL));
    }
    int x = v;
#pragma unroll
    for (int d = 1; d < 32; d <<= 1) {
        int y = __shfl_up_sync(0xffffffffu, x, d);
        if (lane >= d) x += y;
    }
    if (lane == 31) wsum[wq] = x;
    __syncthreads();
    if (wq == 0) {
        int s = wsum[lane];
#pragma unroll
        for (int d = 1; d < 32; d <<= 1) {
            int y = __shfl_up_sync(0xffffffffu, s, d);
            if (lane >= d) s += y;
        }
        wsum[lane] = s;
    }
    __syncthreads();
    int base = wq ? wsum[wq - 1] : 0;
    if (i < NODES) g_cursor[i] = base + x - v;
    if (t == 0) g_bsum[b] = wsum[31];
}

// ---------------- K3: scatter (inline bsum prefix, 4 edges/thread) + sentinels ----------------
__global__ void k_scatter(const int* __restrict__ idx, const float* __restrict__ w,
                          int E, int Epad) {
    __shared__ int s_boff[128];
    __shared__ int s_wt[4];
    int t = threadIdx.x;
    int lane = t & 31, wq = t >> 5;
    int v = 0, x = 0;
    if (t < 128) {
        v = (t < NB) ? g_bsum[t] : 0;
        x = v;
#pragma unroll
        for (int d = 1; d < 32; d <<= 1) {
            int y = __shfl_up_sync(0xffffffffu, x, d);
            if (lane >= d) x += y;
        }
        if (lane == 31) s_wt[wq] = x;
    }
    __syncthreads();
    if (t < 128) {
        int addv = 0;
#pragma unroll
        for (int k = 0; k < 4; k++) if (k < wq) addv += s_wt[k];
        s_boff[t] = addv + x - v;
    }
    __syncthreads();
    int i = blockIdx.x * blockDim.x + t;
    if (i < Epad - E)                                    // sentinel tail (<=1023 entries)
        g_pack[E + i] = make_uint4(0u, (unsigned)NODES, 0u, 0u);
    int e = i * 4;
    if (e + 3 < E) {
        int4   nn = *(const int4*)(idx + e);
        float4 ww = *(const float4*)(w + e);
        int p0 = atomicAdd(&g_cursor[nn.x], 1) + s_boff[nn.x >> 10];
        int p1 = atomicAdd(&g_cursor[nn.y], 1) + s_boff[nn.y >> 10];
        int p2 = atomicAdd(&g_cursor[nn.z], 1) + s_boff[nn.z >> 10];
        int p3 = atomicAdd(&g_cursor[nn.w], 1) + s_boff[nn.w >> 10];
        g_pack[p0] = make_uint4((unsigned)e,       (unsigned)nn.x, __float_as_uint(ww.x), 0u);
        g_pack[p1] = make_uint4((unsigned)(e + 1), (unsigned)nn.y, __float_as_uint(ww.y), 0u);
        g_pack[p2] = make_uint4((unsigned)(e + 2), (unsigned)nn.z, __float_as_uint(ww.z), 0u);
        g_pack[p3] = make_uint4((unsigned)(e + 3), (unsigned)nn.w, __float_as_uint(ww.w), 0u);
    } else {
        for (int k = e; k < E; k++) {
            int n = idx[k];
            int p = atomicAdd(&g_cursor[n], 1) + s_boff[n >> 10];
            g_pack[p] = make_uint4((unsigned)k, (unsigned)n, __float_as_uint(w[k]), 0u);
        }
    }
}

// ---------------- K4: cp.async-pipelined transposed MMA, 32-edge windows ----------------
__global__ void __launch_bounds__(128, 6)
k_main(const float* __restrict__ emb, const float* __restrict__ cf,
       float* __restrict__ out, int E) {
    __shared__ __align__(16) uint4 s_pk[4][PKS][32];      // 8 KB
    __shared__ __align__(16) float s_gb[4][GSS][512];     // 24 KB

    int t = threadIdx.x, wp = t >> 5, l = t & 31;
    int c = l & 3, r4 = l >> 2;
    int wb = (blockIdx.x * 4 + wp) * (NW2 * 32);

    // --- A fragments, K-permuted (slot c holds k=4c+j, matching quarter-major B).
    //     A keeps cvt.rna (amortized); B uses raw-f32 truncation in the hot loop. ---
    unsigned A[4][2][4];
#pragma unroll
    for (int mt = 0; mt < 4; mt++)
#pragma unroll
        for (int kt = 0; kt < 2; kt++) {
            const float* p = emb + (mt * 16 + r4) * 16 + 4 * c + 2 * kt;
            A[mt][kt][0] = f2tf32(__ldg(p));
            A[mt][kt][1] = f2tf32(__ldg(p + 128));
            A[mt][kt][2] = f2tf32(__ldg(p + 1));
            A[mt][kt][3] = f2tf32(__ldg(p + 129));
        }

    int nback = -2, nfwd = -2;
    if (wb > 0)              nback = (int)__ldg(&g_pack[wb - 1]).y;
    if (wb + NW2 * 32 < E)   nfwd  = (int)__ldg(&g_pack[wb + NW2 * 32]).y;

    // --- prologue: packs for windows 0..3 (full ring), then gathers 0,1 ---
#pragma unroll
    for (int h = 0; h < 4; h++) {
        int i = l + h * 32;
        CPA16(sptr(&s_pk[wp][i >> 5][i & 31]), g_pack + wb + i);
    }
    CPCOMMIT();
    CPWAIT(0); __syncwarp();
#pragma unroll
    for (int g = 0; g < 2; g++) {
#pragma unroll
        for (int h = 0; h < 4; h++) {
            int i = l + h * 32;
            unsigned eid = s_pk[wp][g][i >> 2].x;
            CPA16(sptr(&s_gb[wp][g][i * 4]), cf + (size_t)eid * 16 + (i & 3) * 4);
        }
        CPCOMMIT();
    }

    float acc[4][2];
#pragma unroll
    for (int mt = 0; mt < 4; mt++) { acc[mt][0] = 0.f; acc[mt][1] = 0.f; }
    int acc_node = -1;
    bool first = true;
    int prev_last = 0;

#pragma unroll 1
    for (int j = 0; j < NW2; j++) {
        // Group(j-2) = {gather j, pack j+2} completes here; Group(j-1) may pend.
        CPWAIT(1); __syncwarp();

        uint4 pk = s_pk[wp][j & 3][l];         // lane l = edge l of this 32-edge window
        int   nd = (int)pk.y;
        float wreg = __uint_as_float(pk.z);
        int ndn = __shfl_down_sync(0xffffffffu, nd, 1);
        unsigned bm = __ballot_sync(0xffffffffu, (l < 31) && (nd != ndn)) & 0x7fffffffu;
        int node0 = __shfl_sync(0xffffffffu, nd, 0);

        // --- Group(j): gather j+2 (pack j+2 resident) + pack j+4 ---
        if (j + 2 < NW2) {
            int st = (j + 2) % GSS;
            uint4* pks = s_pk[wp][(j + 2) & 3];
#pragma unroll
            for (int h = 0; h < 4; h++) {
                int i = l + h * 32;
                unsigned eid = pks[i >> 2].x;
                CPA16(sptr(&s_gb[wp][st][i * 4]), cf + (size_t)eid * 16 + (i & 3) * 4);
            }
        }
        if (j + 4 < NW2)
            CPA16(sptr(&s_pk[wp][(j + 4) & 3][l]), g_pack + wb + (j + 4) * 32 + l);
        CPCOMMIT();

        const float* gw = s_gb[wp][j % GSS];

        if (j == 0) acc_node = node0;
        else if (prev_last != node0) {
            seg_write(acc, acc_node, first && (nback == acc_node), out, c, r4);
            first = false;
#pragma unroll
            for (int mt = 0; mt < 4; mt++) { acc[mt][0] = 0.f; acc[mt][1] = 0.f; }
            acc_node = node0;
        }

#pragma unroll
        for (int et = 0; et < 4; et++) {
            if (et > 0 && (bm & (1u << (et * 8 - 1)))) {   // seam before this tile
                seg_write(acc, acc_node, first && (nback == acc_node), out, c, r4);
                first = false;
#pragma unroll
                for (int mt = 0; mt < 4; mt++) { acc[mt][0] = 0.f; acc[mt][1] = 0.f; }
                acc_node = __shfl_sync(0xffffffffu, nd, et * 8);
            }

            float wv = __shfl_sync(0xffffffffu, wreg, et * 8 + r4);
            float4 Bv = *(const float4*)(gw + (et * 8 + r4) * 16 + 4 * c);
            unsigned b0 = __float_as_uint(Bv.x * wv);
            unsigned b1 = __float_as_uint(Bv.y * wv);
            unsigned b2 = __float_as_uint(Bv.z * wv);
            unsigned b3 = __float_as_uint(Bv.w * wv);

            float d[4][4];
#pragma unroll
            for (int mt = 0; mt < 4; mt++) {
                d[mt][0] = 0.f; d[mt][1] = 0.f; d[mt][2] = 0.f; d[mt][3] = 0.f;
                mma_tf32(d[mt][0], d[mt][1], d[mt][2], d[mt][3],
                         A[mt][0][0], A[mt][0][1], A[mt][0][2], A[mt][0][3], b0, b1);
                mma_tf32(d[mt][0], d[mt][1], d[mt][2], d[mt][3],
                         A[mt][1][0], A[mt][1][1], A[mt][1][2], A[mt][1][3], b2, b3);
                d[mt][0] = fmaxf(d[mt][0], 0.f);
                d[mt][1] = fmaxf(d[mt][1], 0.f);
                d[mt][2] = fmaxf(d[mt][2], 0.f);
                d[mt][3] = fmaxf(d[mt][3], 0.f);
            }

            unsigned tb = (bm >> (et * 8)) & 0x7fu;        // intra-tile boundaries
            if (tb == 0) {
#pragma unroll
                for (int mt = 0; mt < 4; mt++) {
                    acc[mt][0] += d[mt][0] + d[mt][1];
                    acc[mt][1] += d[mt][2] + d[mt][3];
                }
            } else {
                int sid0 = __popc(tb & ((1u << (2 * c)) - 1));
                int sid1 = sid0 + ((tb >> (2 * c)) & 1);
#pragma unroll
                for (int mt = 0; mt < 4; mt++) {
                    acc[mt][0] += (sid0 == 0 ? d[mt][0] : 0.f) + (sid1 == 0 ? d[mt][1] : 0.f);
                    acc[mt][1] += (sid0 == 0 ? d[mt][2] : 0.f) + (sid1 == 0 ? d[mt][3] : 0.f);
                }
                seg_write(acc, acc_node, first && (nback == acc_node), out, c, r4);
                first = false;
                int last = __popc(tb);
                unsigned rem = tb;
                for (int s = 1; s <= last; s++) {
                    int pos = __ffs(rem) - 1;  rem &= rem - 1;
                    int node_s = __shfl_sync(0xffffffffu, nd, et * 8 + pos + 1);
                    if (s < last) {
                        float vv[4][2];
#pragma unroll
                        for (int mt = 0; mt < 4; mt++) {
                            vv[mt][0] = (sid0 == s ? d[mt][0] : 0.f) + (sid1 == s ? d[mt][1] : 0.f);
                            vv[mt][1] = (sid0 == s ? d[mt][2] : 0.f) + (sid1 == s ? d[mt][3] : 0.f);
                        }
                        seg_write(vv, node_s, false, out, c, r4);
                    } else {
#pragma unroll
                        for (int mt = 0; mt < 4; mt++) {
                            acc[mt][0] = (sid0 == s ? d[mt][0] : 0.f) + (sid1 == s ? d[mt][1] : 0.f);
                            acc[mt][1] = (sid0 == s ? d[mt][2] : 0.f) + (sid1 == s ? d[mt][3] : 0.f);
                        }
                        acc_node = node_s;
                    }
                }
            }
        }

        prev_last = __shfl_sync(0xffffffffu, nd, 31);
    }

    bool use_red = (first && (nback == acc_node)) || (nfwd == acc_node);
    seg_write(acc, acc_node, use_red, out, c, r4);
    CPWAIT(0);                                  // drain before exit
}

// ---------------- launch ----------------
extern "C" void kernel_launch(void* const* d_in, const int* in_sizes, int n_in,
                              void* d_out, int out_size) {
    const float* emb = (const float*)d_in[0];   // [64,16]
    const float* cf  = (const float*)d_in[1];   // [E,16]
    const float* w   = (const float*)d_in[2];   // [E]
    const int*   idx = (const int*)d_in[3];     // [E]
    int E = in_sizes[2];
    float* out = (float*)d_out;                 // [100000,64]

    int n4 = out_size / 4;
    int Epad = ((E + 1023) / 1024) * 1024;      // 4 warps x 256 edges per block
    int e4b = ((E + 3) / 4 + 255) / 256;

    k_count<<<e4b, 256>>>(idx, w, (float4*)d_out, n4, E);
    k_scan1<<<NB, SCAN_BS>>>();
    k_scatter<<<e4b, 256>>>(idx, w, E, Epad);

    k_main<<<Epad / 1024, 128>>>(emb, cf, out, E);
}